// round 16
// baseline (speedup 1.0000x reference)
#include <cuda_runtime.h>
#include <cuda_bf16.h>
#include <stdint.h>
#include <math.h>

#define BQ   2048
#define HD   64
#define ATTD 1024

typedef unsigned long long ull;

// ================= cp.async =================
__device__ __forceinline__ void cpasync16s(unsigned saddr, const void* g) {
    asm volatile("cp.async.cg.shared.global [%0], [%1], 16;" :: "r"(saddr), "l"(g));
}
__device__ __forceinline__ void cp_commit() { asm volatile("cp.async.commit_group;"); }
__device__ __forceinline__ void cp_wait0()  { asm volatile("cp.async.wait_group 0;"); }
__device__ __forceinline__ void cp_wait1()  { asm volatile("cp.async.wait_group 1;"); }

__device__ __forceinline__ unsigned smem_u32(const void* p) {
    return (unsigned)__cvta_generic_to_shared(p);
}

// ================= HMMA (mma.sync, baseline sm_80+ features) =================
#define LDSM4(r, a) asm volatile( \
    "ldmatrix.sync.aligned.m8n8.x4.shared.b16 {%0,%1,%2,%3}, [%4];" \
    : "=r"((r)[0]), "=r"((r)[1]), "=r"((r)[2]), "=r"((r)[3]) : "r"(a))

#define MMA16816(d, a, b) asm volatile( \
    "mma.sync.aligned.m16n8k16.row.col.f32.bf16.bf16.f32 " \
    "{%0,%1,%2,%3}, {%4,%5,%6,%7}, {%8,%9}, {%0,%1,%2,%3};" \
    : "+f"((d)[0]), "+f"((d)[1]), "+f"((d)[2]), "+f"((d)[3]) \
    : "r"((a)[0]), "r"((a)[1]), "r"((a)[2]), "r"((a)[3]), "r"((b)[0]), "r"((b)[1]))

// ================= device scratch =================
// Counters (g_R, g_empty, g_bnsum, g_bnsum2) start zero (static init) and are
// re-zeroed by their LAST READER, so graph replays start clean.
__device__ float g_dec[BQ * ATTD];
__device__ float g_encR[(size_t)BQ * 64 * HD];
__device__ int   g_rowb[BQ * 64];
__device__ int   g_base[BQ];
__device__ int   g_nnz[BQ];
__device__ float g_scoreP[2][BQ * 64];
__device__ int   g_R;
__device__ float g_empty[BQ];
__device__ float g_x[BQ * ATTD];
__device__ float g_bnsum[ATTD];
__device__ float g_bnsum2[ATTD];
__device__ float g_bna[ATTD];
__device__ float g_bnb[ATTD];
// bf16 split operands
__device__ __align__(16) __nv_bfloat16 g_hAh[BQ * 64],     g_hAl[BQ * 64];
__device__ __align__(16) __nv_bfloat16 g_cAh[BQ * 128],    g_cAl[BQ * 128];
__device__ __align__(16) __nv_bfloat16 g_mAh[BQ * 1024],   g_mAl[BQ * 1024];
__device__ __align__(16) __nv_bfloat16 g_WdH[1024 * 64],   g_WdL[1024 * 64];
__device__ __align__(16) __nv_bfloat16 g_WeH[1024 * 64],   g_WeL[1024 * 64];
__device__ __align__(16) __nv_bfloat16 g_WoH[1024 * 128],  g_WoL[1024 * 128];
__device__ __align__(16) __nv_bfloat16 g_WmH[1024 * 1024], g_WmL[1024 * 1024];
__device__ __align__(16) __nv_bfloat16 g_eRh[(size_t)BQ * 64 * HD];
__device__ __align__(16) __nv_bfloat16 g_eRl[(size_t)BQ * 64 * HD];

// ================= fused weight/activation splits ==============
__device__ __forceinline__ void splitB_body(const float* __restrict__ W,
                                            __nv_bfloat16* __restrict__ Bh,
                                            __nv_bfloat16* __restrict__ Bl,
                                            int KK, int KV, int blk, int tid,
                                            float (*t)[33]) {
    int n0 = (blk & 31) * 32, k0 = (blk >> 5) * 32;
    int tx = tid & 31, ty = tid >> 5;
#pragma unroll
    for (int i = 0; i < 4; i++) {
        int k = k0 + ty + i * 8;
        t[ty + i * 8][tx] = (k < KV) ? W[(size_t)k * 1024 + n0 + tx] : 0.f;
    }
    __syncthreads();
#pragma unroll
    for (int i = 0; i < 4; i++) {
        int n = n0 + ty + i * 8;
        float v = t[tx][ty + i * 8];
        __nv_bfloat16 hi = __float2bfloat16(v);
        Bh[(size_t)n * KK + k0 + tx] = hi;
        Bl[(size_t)n * KK + k0 + tx] = __float2bfloat16(v - __bfloat162float(hi));
    }
}

// blocks [0,64): Wdec  [64,128): Wenc  [128,256): Wout  [256,1280): Wmlp
// [1280,1792): splitA(h)
__global__ void k_mega(const float* __restrict__ h,
                       const float* __restrict__ Wdec, const float* __restrict__ Wenc,
                       const float* __restrict__ Wout, const float* __restrict__ Wmlp) {
    __shared__ float t[32][33];
    int bid = blockIdx.x, tid = threadIdx.x;
    if (bid < 64) {
        splitB_body(Wdec, g_WdH, g_WdL, 64, 64, bid, tid, t);
    } else if (bid < 128) {
        splitB_body(Wenc, g_WeH, g_WeL, 64, 64, bid - 64, tid, t);
    } else if (bid < 256) {
        splitB_body(Wout, g_WoH, g_WoL, 128, 68, bid - 128, tid, t);
    } else if (bid < 1280) {
        splitB_body(Wmlp, g_WmH, g_WmL, 1024, 1024, bid - 256, tid, t);
    } else {
        int i = (bid - 1280) * 256 + tid;     // < BQ*64 = 131072
        float v = h[i];
        __nv_bfloat16 hi = __float2bfloat16(v);
        g_hAh[i] = hi;
        g_hAl[i] = __float2bfloat16(v - __bfloat162float(hi));
    }
}

// ================= social pooling + compaction =================
__global__ void k_pool(const float* __restrict__ h, const float* __restrict__ end_pos) {
    int b = blockIdx.x;
    int s = b >> 6;
    int i = b & 63;
    int tid = threadIdx.x;      // 256
    int d = tid & 63;
    int g = tid >> 6;

    __shared__ __align__(16) float hsh[4096];
    __shared__ __align__(16) float acc[4096];
    __shared__ float px[64], py[64];
    __shared__ int   cellj[64];
    __shared__ int   nz[64];
    __shared__ int   slot_cell[64];
    __shared__ int   sh_base, sh_n;

    for (int u = tid; u < 1024; u += 256) {
        *(float4*)&hsh[u * 4] = *(const float4*)(h + (size_t)s * 4096 + u * 4);
        *(float4*)&acc[u * 4] = make_float4(0.f, 0.f, 0.f, 0.f);
    }
    if (tid < 64) {
        px[tid] = end_pos[(s * 64 + tid) * 2 + 0];
        py[tid] = end_pos[(s * 64 + tid) * 2 + 1];
        nz[tid] = 0;
    }
    __syncthreads();

    if (tid < 64) {
        float ax = px[i], ay = py[i];
        float tlx = ax - 1.0f, tly = ay + 1.0f;
        float brx = ax + 1.0f, bry = ay - 1.0f;
        float ox = px[tid], oy = py[tid];
        bool oob = (ox >= brx) || (ox <= tlx) || (oy >= tly) || (oy <= bry) || (tid == i);
        int c = -1;
        if (!oob) {
            float cx = floorf((ox - tlx) / 2.0f * 8.0f);
            float cy = floorf((tly - oy) / 2.0f * 8.0f);
            c = (int)(cx + cy * 8.0f);
        }
        cellj[tid] = c;
    }
    __syncthreads();

    for (int j = g * 16; j < g * 16 + 16; j++) {
        int c = cellj[j];
        if (c >= 0) {
            atomicAdd(&acc[c * 64 + d], hsh[j * 64 + d]);
            if (d == 0) nz[c] = 1;
        }
    }
    __syncthreads();

    if (tid == 0) {
        int n = 0;
        for (int c = 0; c < 64; c++) if (nz[c]) slot_cell[n++] = c;
        int base = atomicAdd(&g_R, n);
        sh_base = base; sh_n = n;
        g_base[b] = base; g_nnz[b] = n;
    }
    __syncthreads();

    int base = sh_base, n = sh_n;
    for (int u = g; u < n; u += 4) {
        int c = slot_cell[u];
        float v = acc[c * 64 + d];
        size_t off = (size_t)(base + u) * 64 + d;
        g_encR[off] = v;
        __nv_bfloat16 hi = __float2bfloat16(v);
        g_eRh[off] = hi;
        g_eRl[off] = __float2bfloat16(v - __bfloat162float(hi));
        if (d == 0) g_rowb[base + u] = b;
    }
}

// ================= HMMA bf16-split GEMM =================
#define RSTR  72
#define MATB  (128 * RSTR * 2)
#define STAGEB (4 * MATB)
template<int EPI>
__global__ void __launch_bounds__(256) hm_gemm(
    const __nv_bfloat16* __restrict__ Ah, const __nv_bfloat16* __restrict__ Al,
    const __nv_bfloat16* __restrict__ Bh, const __nv_bfloat16* __restrict__ Bl,
    const float* __restrict__ bias, int K,
    float* __restrict__ Cf,
    __nv_bfloat16* __restrict__ Coh, __nv_bfloat16* __restrict__ Col,
    const float* __restrict__ benc, const float* __restrict__ wfull,
    float* __restrict__ empty_out)
{
    extern __shared__ __align__(128) char dsm[];
    unsigned sbase = smem_u32(dsm);
    int tid = threadIdx.x;
    int lane = tid & 31, wid = tid >> 5;
    int m0 = blockIdx.y * 128, n0 = blockIdx.x * 128;
    int mb = (wid >> 2) * 64;
    int nb = (wid & 3) * 32;
    int NC = K >> 6;

    const __nv_bfloat16* gA_h = Ah + (size_t)m0 * K;
    const __nv_bfloat16* gA_l = Al + (size_t)m0 * K;
    const __nv_bfloat16* gB_h = Bh + (size_t)n0 * K;
    const __nv_bfloat16* gB_l = Bl + (size_t)n0 * K;

    auto stage_load = [&](int st, int kc) {
        unsigned so = sbase + st * STAGEB;
        const __nv_bfloat16* gs;
#pragma unroll
        for (int mat = 0; mat < 4; mat++) {
            gs = (mat == 0) ? gA_h : (mat == 1) ? gA_l : (mat == 2) ? gB_h : gB_l;
#pragma unroll
            for (int q = 0; q < 4; q++) {
                int idx = tid + q * 256;
                int r = idx >> 3, c = idx & 7;
                cpasync16s(so + mat * MATB + r * (RSTR * 2) + c * 16,
                           gs + (size_t)r * K + kc * 64 + c * 8);
            }
        }
    };

    float acc[4][4][4];
#pragma unroll
    for (int i = 0; i < 4; i++)
#pragma unroll
        for (int j = 0; j < 4; j++)
#pragma unroll
            for (int k = 0; k < 4; k++) acc[i][j][k] = 0.f;

    int quad = lane >> 3, rin = lane & 7;
    int a_r = (quad & 1) * 8 + rin;
    int a_c = (quad >> 1) * 8;
    int b_r = (quad >> 1) * 8 + rin;
    int b_c = (quad & 1) * 8;

    stage_load(0, 0);
    cp_commit();

    for (int ch = 0; ch < NC; ch++) {
        int st = ch & 1;
        if (ch + 1 < NC) { stage_load(st ^ 1, ch + 1); cp_commit(); cp_wait1(); }
        else cp_wait0();
        __syncthreads();
        unsigned so = sbase + st * STAGEB;

#pragma unroll
        for (int ks = 0; ks < 4; ks++) {
            unsigned fAh[4][4], fAl[4][4], fBh[2][4], fBl[2][4];
#pragma unroll
            for (int mt = 0; mt < 4; mt++) {
                unsigned ad = so + ((mb + mt * 16 + a_r) * RSTR + ks * 16 + a_c) * 2;
                LDSM4(fAh[mt], ad);
                LDSM4(fAl[mt], ad + MATB);
            }
#pragma unroll
            for (int np = 0; np < 2; np++) {
                unsigned bd = so + 2 * MATB + ((nb + np * 16 + b_r) * RSTR + ks * 16 + b_c) * 2;
                LDSM4(fBh[np], bd);
                LDSM4(fBl[np], bd + MATB);
            }
#pragma unroll
            for (int mt = 0; mt < 4; mt++)
#pragma unroll
                for (int nt = 0; nt < 4; nt++) {
                    unsigned* bh = &fBh[nt >> 1][(nt & 1) * 2];
                    unsigned* bl = &fBl[nt >> 1][(nt & 1) * 2];
                    MMA16816(acc[mt][nt], fAh[mt], bh);
                    MMA16816(acc[mt][nt], fAl[mt], bh);
                    MMA16816(acc[mt][nt], fAh[mt], bl);
                }
        }
        __syncthreads();
    }

    // ---- epilogue ----
    int g = lane >> 2;
    int cpos = (lane & 3) * 2;
    float cs[4][2], cq[4][2];
    if (EPI == 2) {
#pragma unroll
        for (int nt = 0; nt < 4; nt++) { cs[nt][0] = cs[nt][1] = 0.f; cq[nt][0] = cq[nt][1] = 0.f; }
    }

#pragma unroll
    for (int mt = 0; mt < 4; mt++) {
        int row = m0 + mb + mt * 16 + g;
        float e0 = 0.f, e1 = 0.f;
#pragma unroll
        for (int nt = 0; nt < 4; nt++) {
            int col = n0 + nb + nt * 8 + cpos;
            float b0v = bias[col], b1v = bias[col + 1];
            float v00 = acc[mt][nt][0] + b0v, v01 = acc[mt][nt][1] + b1v;
            float v10 = acc[mt][nt][2] + b0v, v11 = acc[mt][nt][3] + b1v;
            if (EPI == 1) {
                v00 = fmaxf(v00, 0.f); v01 = fmaxf(v01, 0.f);
                v10 = fmaxf(v10, 0.f); v11 = fmaxf(v11, 0.f);
                __nv_bfloat16 h00 = __float2bfloat16(v00), h01 = __float2bfloat16(v01);
                __nv_bfloat16 h10 = __float2bfloat16(v10), h11 = __float2bfloat16(v11);
                __nv_bfloat162 t;
                t.x = h00; t.y = h01;
                *(__nv_bfloat162*)&Coh[(size_t)row * 1024 + col] = t;
                t.x = h10; t.y = h11;
                *(__nv_bfloat162*)&Coh[(size_t)(row + 8) * 1024 + col] = t;
                t.x = __float2bfloat16(v00 - __bfloat162float(h00));
                t.y = __float2bfloat16(v01 - __bfloat162float(h01));
                *(__nv_bfloat162*)&Col[(size_t)row * 1024 + col] = t;
                t.x = __float2bfloat16(v10 - __bfloat162float(h10));
                t.y = __float2bfloat16(v11 - __bfloat162float(h11));
                *(__nv_bfloat162*)&Col[(size_t)(row + 8) * 1024 + col] = t;
            } else {
                float2 p;
                p.x = v00; p.y = v01;
                *(float2*)&Cf[(size_t)row * 1024 + col] = p;
                p.x = v10; p.y = v11;
                *(float2*)&Cf[(size_t)(row + 8) * 1024 + col] = p;
            }
            if (EPI == 0) {
                float be0 = benc[col], be1 = benc[col + 1];
                float wf0 = wfull[col], wf1 = wfull[col + 1];
                float t;
                t = v00 + be0; if (t > 0.f) e0 += t * wf0;
                t = v01 + be1; if (t > 0.f) e0 += t * wf1;
                t = v10 + be0; if (t > 0.f) e1 += t * wf0;
                t = v11 + be1; if (t > 0.f) e1 += t * wf1;
            }
            if (EPI == 2) {
                cs[nt][0] += v00 + v10; cs[nt][1] += v01 + v11;
                cq[nt][0] += v00 * v00 + v10 * v10;
                cq[nt][1] += v01 * v01 + v11 * v11;
            }
        }
        if (EPI == 0) {
            e0 += __shfl_xor_sync(0xffffffffu, e0, 1);
            e0 += __shfl_xor_sync(0xffffffffu, e0, 2);
            e1 += __shfl_xor_sync(0xffffffffu, e1, 1);
            e1 += __shfl_xor_sync(0xffffffffu, e1, 2);
            if ((lane & 3) == 0) {
                atomicAdd(&empty_out[row], e0);
                atomicAdd(&empty_out[row + 8], e1);
            }
        }
    }
    if (EPI == 2) {
#pragma unroll
        for (int nt = 0; nt < 4; nt++) {
#pragma unroll
            for (int j = 0; j < 2; j++) {
                float s = cs[nt][j], q = cq[nt][j];
                s += __shfl_xor_sync(0xffffffffu, s, 4);
                s += __shfl_xor_sync(0xffffffffu, s, 8);
                s += __shfl_xor_sync(0xffffffffu, s, 16);
                q += __shfl_xor_sync(0xffffffffu, q, 4);
                q += __shfl_xor_sync(0xffffffffu, q, 8);
                q += __shfl_xor_sync(0xffffffffu, q, 16);
                if (lane < 4) {
                    int col = n0 + nb + nt * 8 + cpos + j;
                    atomicAdd(&g_bnsum[col], s);
                    atomicAdd(&g_bnsum2[col], q);
                }
            }
        }
    }
}

// ================= HMMA sparse score GEMM (2 N-halves) ============
__global__ void __launch_bounds__(256, 2) hm_scores(
    const __nv_bfloat16* __restrict__ WeH, const __nv_bfloat16* __restrict__ WeL,
    const float* __restrict__ benc, const float* __restrict__ wfull)
{
    int R = g_R;
    int r0 = blockIdx.x * 128;
    if (r0 >= R) return;
    int half = blockIdx.y;

    extern __shared__ __align__(128) char dsm[];
    unsigned sbase = smem_u32(dsm);
    __shared__ int   rb[128];
    __shared__ float red[128][5];

    int tid = threadIdx.x;
    int lane = tid & 31, wid = tid >> 5;
    int mb = (wid >> 2) * 64;
    int nw = wid & 3;
    int nb = nw * 32;

    if (tid < 128) rb[tid] = (r0 + tid < R) ? g_rowb[r0 + tid] : 0;

#pragma unroll
    for (int q = 0; q < 8; q++) {
        int idx = tid + q * 256;
        int mat = idx >> 10, r = (idx >> 3) & 127, c = idx & 7;
        const __nv_bfloat16* src = mat ? g_eRl : g_eRh;
        cpasync16s(sbase + mat * MATB + r * (RSTR * 2) + c * 16,
                   src + (size_t)(r0 + r) * 64 + c * 8);
    }
    auto stage_loadB = [&](int st, int nt) {
        unsigned so = sbase + 2 * MATB + st * 2 * MATB;
#pragma unroll
        for (int q = 0; q < 8; q++) {
            int idx = tid + q * 256;
            int mat = idx >> 10, r = (idx >> 3) & 127, c = idx & 7;
            const __nv_bfloat16* src = mat ? WeL : WeH;
            cpasync16s(so + mat * MATB + r * (RSTR * 2) + c * 16,
                       src + (size_t)(nt * 128 + r) * 64 + c * 8);
        }
    };
    stage_loadB(0, half * 4);
    cp_commit();

    int quad = lane >> 3, rin = lane & 7;
    int a_r = (quad & 1) * 8 + rin;
    int a_c = (quad >> 1) * 8;
    int b_r = (quad >> 1) * 8 + rin;
    int b_c = (quad & 1) * 8;
    int g = lane >> 2;
    int cpos = (lane & 3) * 2;

    float rs[4][2];
#pragma unroll
    for (int mt = 0; mt < 4; mt++) { rs[mt][0] = 0.f; rs[mt][1] = 0.f; }

    for (int tt = 0; tt < 4; tt++) {
        int ti = half * 4 + tt;
        int st = tt & 1;
        if (tt + 1 < 4) { stage_loadB(st ^ 1, ti + 1); cp_commit(); cp_wait1(); }
        else cp_wait0();
        __syncthreads();
        unsigned bo = sbase + 2 * MATB + st * 2 * MATB;

        float acc[4][4][4];
#pragma unroll
        for (int i = 0; i < 4; i++)
#pragma unroll
            for (int j = 0; j < 4; j++)
#pragma unroll
                for (int k = 0; k < 4; k++) acc[i][j][k] = 0.f;

#pragma unroll
        for (int ks = 0; ks < 4; ks++) {
            unsigned fAh[4][4], fAl[4][4], fBh[2][4], fBl[2][4];
#pragma unroll
            for (int mt = 0; mt < 4; mt++) {
                unsigned ad = sbase + ((mb + mt * 16 + a_r) * RSTR + ks * 16 + a_c) * 2;
                LDSM4(fAh[mt], ad);
                LDSM4(fAl[mt], ad + MATB);
            }
#pragma unroll
            for (int np = 0; np < 2; np++) {
                unsigned bd = bo + ((nb + np * 16 + b_r) * RSTR + ks * 16 + b_c) * 2;
                LDSM4(fBh[np], bd);
                LDSM4(fBl[np], bd + MATB);
            }
#pragma unroll
            for (int mt = 0; mt < 4; mt++)
#pragma unroll
                for (int nt = 0; nt < 4; nt++) {
                    unsigned* bh = &fBh[nt >> 1][(nt & 1) * 2];
                    unsigned* bl = &fBl[nt >> 1][(nt & 1) * 2];
                    MMA16816(acc[mt][nt], fAh[mt], bh);
                    MMA16816(acc[mt][nt], fAl[mt], bh);
                    MMA16816(acc[mt][nt], fAh[mt], bl);
                }
        }

#pragma unroll
        for (int nt = 0; nt < 4; nt++) {
            int col = ti * 128 + nb + nt * 8 + cpos;
            float be0 = benc[col], be1 = benc[col + 1];
            float wf0 = wfull[col], wf1 = wfull[col + 1];
#pragma unroll
            for (int mt = 0; mt < 4; mt++) {
                int rl0 = mb + mt * 16 + g;
                float2 d0 = *(const float2*)&g_dec[(size_t)rb[rl0] * 1024 + col];
                float2 d1 = *(const float2*)&g_dec[(size_t)rb[rl0 + 8] * 1024 + col];
                float v;
                v = acc[mt][nt][0] + be0 + d0.x; if (v > 0.f) rs[mt][0] += v * wf0;
                v = acc[mt][nt][1] + be1 + d0.y; if (v > 0.f) rs[mt][0] += v * wf1;
                v = acc[mt][nt][2] + be0 + d1.x; if (v > 0.f) rs[mt][1] += v * wf0;
                v = acc[mt][nt][3] + be1 + d1.y; if (v > 0.f) rs[mt][1] += v * wf1;
            }
        }
        __syncthreads();
    }

#pragma unroll
    for (int mt = 0; mt < 4; mt++) {
#pragma unroll
        for (int hh = 0; hh < 2; hh++) {
            float r = rs[mt][hh];
            r += __shfl_xor_sync(0xffffffffu, r, 1);
            r += __shfl_xor_sync(0xffffffffu, r, 2);
            if ((lane & 3) == 0) red[mb + mt * 16 + g + hh * 8][nw] = r;
        }
    }
    __syncthreads();
    if (tid < 128 && r0 + tid < R) {
        g_scoreP[half][r0 + tid] = red[tid][0] + red[tid][1] + red[tid][2] + red[tid][3];
    }
}

// ================= softmax + ctx + embed (256 thr, parallel gather) ===========
__global__ void k_softctx(const float* __restrict__ bfull, const float* __restrict__ end_pos,
                          const float* __restrict__ rel_pos, const float* __restrict__ Wemb,
                          const float* __restrict__ bemb) {
    int b = blockIdx.x;
    int tid = threadIdx.x;  // 256
    __shared__ float sc[64];
    __shared__ float alpha[64];
    __shared__ float part[4][64];
    __shared__ float sh_se;

    int base = g_base[b], nnz = g_nnz[b];
    float bf0 = bfull[0];
    if (tid < nnz) sc[tid] = g_scoreP[0][base + tid] + g_scoreP[1][base + tid] + bf0;
    if (tid == 0) {
        sh_se = g_empty[b] + bf0;
        g_empty[b] = 0.f;                 // reset for next launch
        if (b == 0) g_R = 0;
    }
    __syncthreads();

    if (tid < 32) {
        float se = sh_se;
        float m = se;
        float v0 = (tid < nnz) ? sc[tid] : -1e30f;
        float v1 = (tid + 32 < nnz) ? sc[tid + 32] : -1e30f;
        m = fmaxf(m, fmaxf(v0, v1));
#pragma unroll
        for (int o = 16; o > 0; o >>= 1) m = fmaxf(m, __shfl_xor_sync(0xffffffffu, m, o));
        float e0 = (tid < nnz) ? expf(v0 - m) : 0.f;
        float e1 = (tid + 32 < nnz) ? expf(v1 - m) : 0.f;
        float z = e0 + e1;
#pragma unroll
        for (int o = 16; o > 0; o >>= 1) z += __shfl_xor_sync(0xffffffffu, z, o);
        z += (float)(64 - nnz) * expf(se - m);
        float inv = 1.0f / z;
        if (tid < nnz) alpha[tid] = e0 * inv;
        if (tid + 32 < nnz) alpha[tid + 32] = e1 * inv;
    }
    __syncthreads();

    // ctx partials: 4 slices x 64 dims
    int d = tid & 63, sl = tid >> 6;
    float c = 0.f;
    for (int t = sl; t < nnz; t += 4)
        c += alpha[t] * g_encR[(size_t)(base + t) * 64 + d];
    part[sl][d] = c;
    __syncthreads();

    if (tid < 128) {
        float v;
        if (tid < 64) {
            v = part[0][tid] + part[1][tid] + part[2][tid] + part[3][tid];
        } else if (tid < 68) {
            int j = tid - 64;
            float e = end_pos[b * 2 + 0] * Wemb[0 * 4 + j] + end_pos[b * 2 + 1] * Wemb[1 * 4 + j]
                    + rel_pos[b * 2 + 0] * Wemb[2 * 4 + j] + rel_pos[b * 2 + 1] * Wemb[3 * 4 + j]
                    + bemb[j];
            v = fmaxf(e, 0.f);
        } else {
            v = 0.f;
        }
        __nv_bfloat16 hi = __float2bfloat16(v);
        g_cAh[b * 128 + tid] = hi;
        g_cAl[b * 128 + tid] = __float2bfloat16(v - __bfloat162float(hi));
    }
}

// ================= batchnorm final (resets sums) + apply =================
__global__ void k_bnfinal(const float* __restrict__ gamma, const float* __restrict__ beta) {
    int c = threadIdx.x;
    float mu = g_bnsum[c] / (float)BQ;
    float var = g_bnsum2[c] / (float)BQ - mu * mu;
    float rstd = rsqrtf(var + 1e-5f);
    float ga = gamma[c] * rstd;
    g_bna[c] = ga;
    g_bnb[c] = beta[c] - mu * ga;
    g_bnsum[c] = 0.f;
    g_bnsum2[c] = 0.f;
}

__global__ void k_bnapply(float* __restrict__ out) {
    int idx = blockIdx.x * blockDim.x + threadIdx.x;
    if (idx < BQ * ATTD) {
        int c = idx & 1023;
        float v = g_x[idx] * g_bna[c] + g_bnb[c];
        out[idx] = v > 0.f ? v : 0.f;
    }
}

// ================= launch =================
extern "C" void kernel_launch(void* const* d_in, const int* in_sizes, int n_in,
                              void* d_out, int out_size) {
    const float* h       = (const float*)d_in[0];
    const float* end_pos = (const float*)d_in[2];
    const float* rel_pos = (const float*)d_in[3];
    const float* Wenc    = (const float*)d_in[4];
    const float* benc    = (const float*)d_in[5];
    const float* Wdec    = (const float*)d_in[6];
    const float* bdec    = (const float*)d_in[7];
    const float* wfull   = (const float*)d_in[8];
    const float* bfull   = (const float*)d_in[9];
    const float* Wemb    = (const float*)d_in[10];
    const float* bemb    = (const float*)d_in[11];
    const float* Wout    = (const float*)d_in[12];
    const float* bout    = (const float*)d_in[13];
    const float* Wmlp    = (const float*)d_in[14];
    const float* bmlp    = (const float*)d_in[15];
    const float* gamma   = (const float*)d_in[16];
    const float* beta    = (const float*)d_in[17];
    float* out = (float*)d_out;

    float *p_dec, *p_x, *p_empty;
    __nv_bfloat16 *p_hAh, *p_hAl, *p_cAh, *p_cAl, *p_mAh, *p_mAl;
    __nv_bfloat16 *p_WdH, *p_WdL, *p_WeH, *p_WeL, *p_WoH, *p_WoL, *p_WmH, *p_WmL;
    cudaGetSymbolAddress((void**)&p_dec,   g_dec);
    cudaGetSymbolAddress((void**)&p_x,     g_x);
    cudaGetSymbolAddress((void**)&p_empty, g_empty);
    cudaGetSymbolAddress((void**)&p_hAh, g_hAh); cudaGetSymbolAddress((void**)&p_hAl, g_hAl);
    cudaGetSymbolAddress((void**)&p_cAh, g_cAh); cudaGetSymbolAddress((void**)&p_cAl, g_cAl);
    cudaGetSymbolAddress((void**)&p_mAh, g_mAh); cudaGetSymbolAddress((void**)&p_mAl, g_mAl);
    cudaGetSymbolAddress((void**)&p_WdH, g_WdH); cudaGetSymbolAddress((void**)&p_WdL, g_WdL);
    cudaGetSymbolAddress((void**)&p_WeH, g_WeH); cudaGetSymbolAddress((void**)&p_WeL, g_WeL);
    cudaGetSymbolAddress((void**)&p_WoH, g_WoH); cudaGetSymbolAddress((void**)&p_WoL, g_WoL);
    cudaGetSymbolAddress((void**)&p_WmH, g_WmH); cudaGetSymbolAddress((void**)&p_WmL, g_WmL);

    const int DSM  = 2 * STAGEB;     // 147456 (hm_gemm)
    const int DSMS = 6 * MATB;       // 110592 (hm_scores)
    cudaFuncSetAttribute(hm_gemm<0>, cudaFuncAttributeMaxDynamicSharedMemorySize, DSM);
    cudaFuncSetAttribute(hm_gemm<1>, cudaFuncAttributeMaxDynamicSharedMemorySize, DSM);
    cudaFuncSetAttribute(hm_gemm<2>, cudaFuncAttributeMaxDynamicSharedMemorySize, DSM);
    cudaFuncSetAttribute(hm_scores,  cudaFuncAttributeMaxDynamicSharedMemorySize, DSMS);

    dim3 gg(8, 16);  // 1024/128 x 2048/128
    dim3 gs(BQ * 64 / 128, 2);

    k_mega<<<1792, 256>>>(h, Wdec, Wenc, Wout, Wmlp);
    k_pool<<<BQ, 256>>>(h, end_pos);
    hm_gemm<0><<<gg, 256, DSM>>>(p_hAh, p_hAl, p_WdH, p_WdL, bdec, 64,
                                 p_dec, nullptr, nullptr, benc, wfull, p_empty);
    hm_scores<<<gs, 256, DSMS>>>(p_WeH, p_WeL, benc, wfull);
    k_softctx<<<BQ, 256>>>(bfull, end_pos, rel_pos, Wemb, bemb);
    hm_gemm<1><<<gg, 256, DSM>>>(p_cAh, p_cAl, p_WoH, p_WoL, bout, 128,
                                 nullptr, p_mAh, p_mAl, nullptr, nullptr, nullptr);
    hm_gemm<2><<<gg, 256, DSM>>>(p_mAh, p_mAl, p_WmH, p_WmL, bmlp, 1024,
                                 p_x, nullptr, nullptr, nullptr, nullptr, nullptr);
    k_bnfinal<<<1, 1024>>>(gamma, beta);
    k_bnapply<<<(BQ * ATTD + 255) / 256, 256>>>(out);
}

// round 17
// speedup vs baseline: 1.1477x; 1.1477x over previous
#include <cuda_runtime.h>
#include <cuda_bf16.h>
#include <stdint.h>
#include <math.h>

#define BQ   2048
#define HD   64
#define ATTD 1024

typedef unsigned long long ull;

// ================= cp.async =================
__device__ __forceinline__ void cpasync16s(unsigned saddr, const void* g) {
    asm volatile("cp.async.cg.shared.global [%0], [%1], 16;" :: "r"(saddr), "l"(g));
}
__device__ __forceinline__ void cp_commit() { asm volatile("cp.async.commit_group;"); }
__device__ __forceinline__ void cp_wait0()  { asm volatile("cp.async.wait_group 0;"); }
__device__ __forceinline__ void cp_wait1()  { asm volatile("cp.async.wait_group 1;"); }

__device__ __forceinline__ unsigned smem_u32(const void* p) {
    return (unsigned)__cvta_generic_to_shared(p);
}

// ================= HMMA (mma.sync, baseline sm_80+ features) =================
#define LDSM4(r, a) asm volatile( \
    "ldmatrix.sync.aligned.m8n8.x4.shared.b16 {%0,%1,%2,%3}, [%4];" \
    : "=r"((r)[0]), "=r"((r)[1]), "=r"((r)[2]), "=r"((r)[3]) : "r"(a))

#define MMA16816(d, a, b) asm volatile( \
    "mma.sync.aligned.m16n8k16.row.col.f32.bf16.bf16.f32 " \
    "{%0,%1,%2,%3}, {%4,%5,%6,%7}, {%8,%9}, {%0,%1,%2,%3};" \
    : "+f"((d)[0]), "+f"((d)[1]), "+f"((d)[2]), "+f"((d)[3]) \
    : "r"((a)[0]), "r"((a)[1]), "r"((a)[2]), "r"((a)[3]), "r"((b)[0]), "r"((b)[1]))

// ================= device scratch =================
__device__ float g_dec[BQ * ATTD];
__device__ float g_encR[(size_t)BQ * 64 * HD];
__device__ int   g_rowb[BQ * 64];
__device__ int   g_base[BQ];
__device__ int   g_nnz[BQ];
__device__ float g_scoreP[2][BQ * 64];     // partial scores (two N-halves)
__device__ int   g_R;
__device__ float g_empty[BQ];
__device__ float g_x[BQ * ATTD];
__device__ float g_bnsum[ATTD];
__device__ float g_bnsum2[ATTD];
__device__ float g_bna[ATTD];
__device__ float g_bnb[ATTD];
// bf16 split operands (16B aligned for cp.async)
__device__ __align__(16) __nv_bfloat16 g_hAh[BQ * 64],     g_hAl[BQ * 64];
__device__ __align__(16) __nv_bfloat16 g_cAh[BQ * 128],    g_cAl[BQ * 128];
__device__ __align__(16) __nv_bfloat16 g_mAh[BQ * 1024],   g_mAl[BQ * 1024];
__device__ __align__(16) __nv_bfloat16 g_WdH[1024 * 64],   g_WdL[1024 * 64];
__device__ __align__(16) __nv_bfloat16 g_WeH[1024 * 64],   g_WeL[1024 * 64];
__device__ __align__(16) __nv_bfloat16 g_WoH[1024 * 128],  g_WoL[1024 * 128];
__device__ __align__(16) __nv_bfloat16 g_WmH[1024 * 1024], g_WmL[1024 * 1024];
__device__ __align__(16) __nv_bfloat16 g_eRh[(size_t)BQ * 64 * HD];
__device__ __align__(16) __nv_bfloat16 g_eRl[(size_t)BQ * 64 * HD];

// ================= fused prologue: all splits + counter zeroing ==============
__device__ __forceinline__ void splitB_body(const float* __restrict__ W,
                                            __nv_bfloat16* __restrict__ Bh,
                                            __nv_bfloat16* __restrict__ Bl,
                                            int KK, int KV, int blk, int tid,
                                            float (*t)[33]) {
    int n0 = (blk & 31) * 32, k0 = (blk >> 5) * 32;
    int tx = tid & 31, ty = tid >> 5;   // 32 x 8
#pragma unroll
    for (int i = 0; i < 4; i++) {
        int k = k0 + ty + i * 8;
        t[ty + i * 8][tx] = (k < KV) ? W[(size_t)k * 1024 + n0 + tx] : 0.f;
    }
    __syncthreads();
#pragma unroll
    for (int i = 0; i < 4; i++) {
        int n = n0 + ty + i * 8;
        float v = t[tx][ty + i * 8];
        __nv_bfloat16 hi = __float2bfloat16(v);
        Bh[(size_t)n * KK + k0 + tx] = hi;
        Bl[(size_t)n * KK + k0 + tx] = __float2bfloat16(v - __bfloat162float(hi));
    }
}

__global__ void k_mega(const float* __restrict__ h,
                       const float* __restrict__ Wdec, const float* __restrict__ Wenc,
                       const float* __restrict__ Wout, const float* __restrict__ Wmlp) {
    __shared__ float t[32][33];
    int bid = blockIdx.x, tid = threadIdx.x;
    if (bid < 64) {
        splitB_body(Wdec, g_WdH, g_WdL, 64, 64, bid, tid, t);
    } else if (bid < 128) {
        splitB_body(Wenc, g_WeH, g_WeL, 64, 64, bid - 64, tid, t);
    } else if (bid < 256) {
        splitB_body(Wout, g_WoH, g_WoL, 128, 68, bid - 128, tid, t);
    } else if (bid < 1280) {
        splitB_body(Wmlp, g_WmH, g_WmL, 1024, 1024, bid - 256, tid, t);
    } else if (bid < 1792) {
        int i = (bid - 1280) * 256 + tid;     // < BQ*64 = 131072
        float v = h[i];
        __nv_bfloat16 hi = __float2bfloat16(v);
        g_hAh[i] = hi;
        g_hAl[i] = __float2bfloat16(v - __bfloat162float(hi));
    } else {
        int i = (bid - 1792) * 256 + tid;     // < 2048
        if (i < ATTD) { g_bnsum[i] = 0.f; g_bnsum2[i] = 0.f; }
        g_empty[i] = 0.f;
        if (i == 0) g_R = 0;
    }
}

// ================= social pooling + compaction (emit fp32 + bf16 split) =======
__global__ void k_pool(const float* __restrict__ h, const float* __restrict__ end_pos) {
    int b = blockIdx.x;
    int s = b >> 6;
    int i = b & 63;
    int tid = threadIdx.x;      // 256
    int d = tid & 63;
    int g = tid >> 6;

    __shared__ __align__(16) float hsh[4096];
    __shared__ __align__(16) float acc[4096];
    __shared__ float px[64], py[64];
    __shared__ int   cellj[64];
    __shared__ int   nz[64];
    __shared__ int   slot_cell[64];
    __shared__ int   sh_base, sh_n;

    for (int u = tid; u < 1024; u += 256) {
        *(float4*)&hsh[u * 4] = *(const float4*)(h + (size_t)s * 4096 + u * 4);
        *(float4*)&acc[u * 4] = make_float4(0.f, 0.f, 0.f, 0.f);
    }
    if (tid < 64) {
        px[tid] = end_pos[(s * 64 + tid) * 2 + 0];
        py[tid] = end_pos[(s * 64 + tid) * 2 + 1];
        nz[tid] = 0;
    }
    __syncthreads();

    if (tid < 64) {
        float ax = px[i], ay = py[i];
        float tlx = ax - 1.0f, tly = ay + 1.0f;
        float brx = ax + 1.0f, bry = ay - 1.0f;
        float ox = px[tid], oy = py[tid];
        bool oob = (ox >= brx) || (ox <= tlx) || (oy >= tly) || (oy <= bry) || (tid == i);
        int c = -1;
        if (!oob) {
            float cx = floorf((ox - tlx) / 2.0f * 8.0f);
            float cy = floorf((tly - oy) / 2.0f * 8.0f);
            c = (int)(cx + cy * 8.0f);
        }
        cellj[tid] = c;
    }
    __syncthreads();

    for (int j = g * 16; j < g * 16 + 16; j++) {
        int c = cellj[j];
        if (c >= 0) {
            atomicAdd(&acc[c * 64 + d], hsh[j * 64 + d]);
            if (d == 0) nz[c] = 1;
        }
    }
    __syncthreads();

    if (tid == 0) {
        int n = 0;
        for (int c = 0; c < 64; c++) if (nz[c]) slot_cell[n++] = c;
        int base = atomicAdd(&g_R, n);
        sh_base = base; sh_n = n;
        g_base[b] = base; g_nnz[b] = n;
    }
    __syncthreads();

    int base = sh_base, n = sh_n;
    for (int u = g; u < n; u += 4) {
        int c = slot_cell[u];
        float v = acc[c * 64 + d];
        size_t off = (size_t)(base + u) * 64 + d;
        g_encR[off] = v;
        __nv_bfloat16 hi = __float2bfloat16(v);
        g_eRh[off] = hi;
        g_eRl[off] = __float2bfloat16(v - __bfloat162float(hi));
        if (d == 0) g_rowb[base + u] = b;
    }
}

// ================= HMMA bf16-split GEMM =================
#define RSTR  72
#define MATB  (128 * RSTR * 2)
#define STAGEB (4 * MATB)
template<int EPI>
__global__ void __launch_bounds__(256) hm_gemm(
    const __nv_bfloat16* __restrict__ Ah, const __nv_bfloat16* __restrict__ Al,
    const __nv_bfloat16* __restrict__ Bh, const __nv_bfloat16* __restrict__ Bl,
    const float* __restrict__ bias, int K,
    float* __restrict__ Cf,
    __nv_bfloat16* __restrict__ Coh, __nv_bfloat16* __restrict__ Col,
    const float* __restrict__ benc, const float* __restrict__ wfull,
    float* __restrict__ empty_out)
{
    extern __shared__ __align__(128) char dsm[];
    unsigned sbase = smem_u32(dsm);
    int tid = threadIdx.x;
    int lane = tid & 31, wid = tid >> 5;
    int m0 = blockIdx.y * 128, n0 = blockIdx.x * 128;
    int mb = (wid >> 2) * 64;
    int nb = (wid & 3) * 32;
    int NC = K >> 6;

    const __nv_bfloat16* gA_h = Ah + (size_t)m0 * K;
    const __nv_bfloat16* gA_l = Al + (size_t)m0 * K;
    const __nv_bfloat16* gB_h = Bh + (size_t)n0 * K;
    const __nv_bfloat16* gB_l = Bl + (size_t)n0 * K;

    auto stage_load = [&](int st, int kc) {
        unsigned so = sbase + st * STAGEB;
        const __nv_bfloat16* gs;
#pragma unroll
        for (int mat = 0; mat < 4; mat++) {
            gs = (mat == 0) ? gA_h : (mat == 1) ? gA_l : (mat == 2) ? gB_h : gB_l;
#pragma unroll
            for (int q = 0; q < 4; q++) {
                int idx = tid + q * 256;
                int r = idx >> 3, c = idx & 7;
                cpasync16s(so + mat * MATB + r * (RSTR * 2) + c * 16,
                           gs + (size_t)r * K + kc * 64 + c * 8);
            }
        }
    };

    float acc[4][4][4];
#pragma unroll
    for (int i = 0; i < 4; i++)
#pragma unroll
        for (int j = 0; j < 4; j++)
#pragma unroll
            for (int k = 0; k < 4; k++) acc[i][j][k] = 0.f;

    int quad = lane >> 3, rin = lane & 7;
    int a_r = (quad & 1) * 8 + rin;
    int a_c = (quad >> 1) * 8;
    int b_r = (quad >> 1) * 8 + rin;
    int b_c = (quad & 1) * 8;

    stage_load(0, 0);
    cp_commit();

    for (int ch = 0; ch < NC; ch++) {
        int st = ch & 1;
        if (ch + 1 < NC) { stage_load(st ^ 1, ch + 1); cp_commit(); cp_wait1(); }
        else cp_wait0();
        __syncthreads();
        unsigned so = sbase + st * STAGEB;

#pragma unroll
        for (int ks = 0; ks < 4; ks++) {
            unsigned fAh[4][4], fAl[4][4], fBh[2][4], fBl[2][4];
#pragma unroll
            for (int mt = 0; mt < 4; mt++) {
                unsigned ad = so + ((mb + mt * 16 + a_r) * RSTR + ks * 16 + a_c) * 2;
                LDSM4(fAh[mt], ad);
                LDSM4(fAl[mt], ad + MATB);
            }
#pragma unroll
            for (int np = 0; np < 2; np++) {
                unsigned bd = so + 2 * MATB + ((nb + np * 16 + b_r) * RSTR + ks * 16 + b_c) * 2;
                LDSM4(fBh[np], bd);
                LDSM4(fBl[np], bd + MATB);
            }
#pragma unroll
            for (int mt = 0; mt < 4; mt++)
#pragma unroll
                for (int nt = 0; nt < 4; nt++) {
                    unsigned* bh = &fBh[nt >> 1][(nt & 1) * 2];
                    unsigned* bl = &fBl[nt >> 1][(nt & 1) * 2];
                    MMA16816(acc[mt][nt], fAh[mt], bh);
                    MMA16816(acc[mt][nt], fAl[mt], bh);
                    MMA16816(acc[mt][nt], fAh[mt], bl);
                }
        }
        __syncthreads();
    }

    // ---- epilogue ----
    int g = lane >> 2;
    int cpos = (lane & 3) * 2;
    float cs[4][2], cq[4][2];
    if (EPI == 2) {
#pragma unroll
        for (int nt = 0; nt < 4; nt++) { cs[nt][0] = cs[nt][1] = 0.f; cq[nt][0] = cq[nt][1] = 0.f; }
    }

#pragma unroll
    for (int mt = 0; mt < 4; mt++) {
        int row = m0 + mb + mt * 16 + g;
        float e0 = 0.f, e1 = 0.f;
#pragma unroll
        for (int nt = 0; nt < 4; nt++) {
            int col = n0 + nb + nt * 8 + cpos;
            float b0v = bias[col], b1v = bias[col + 1];
            float v00 = acc[mt][nt][0] + b0v, v01 = acc[mt][nt][1] + b1v;
            float v10 = acc[mt][nt][2] + b0v, v11 = acc[mt][nt][3] + b1v;
            if (EPI == 1) {
                v00 = fmaxf(v00, 0.f); v01 = fmaxf(v01, 0.f);
                v10 = fmaxf(v10, 0.f); v11 = fmaxf(v11, 0.f);
                __nv_bfloat16 h00 = __float2bfloat16(v00), h01 = __float2bfloat16(v01);
                __nv_bfloat16 h10 = __float2bfloat16(v10), h11 = __float2bfloat16(v11);
                __nv_bfloat162 t;
                t.x = h00; t.y = h01;
                *(__nv_bfloat162*)&Coh[(size_t)row * 1024 + col] = t;
                t.x = h10; t.y = h11;
                *(__nv_bfloat162*)&Coh[(size_t)(row + 8) * 1024 + col] = t;
                t.x = __float2bfloat16(v00 - __bfloat162float(h00));
                t.y = __float2bfloat16(v01 - __bfloat162float(h01));
                *(__nv_bfloat162*)&Col[(size_t)row * 1024 + col] = t;
                t.x = __float2bfloat16(v10 - __bfloat162float(h10));
                t.y = __float2bfloat16(v11 - __bfloat162float(h11));
                *(__nv_bfloat162*)&Col[(size_t)(row + 8) * 1024 + col] = t;
            } else {
                float2 p;
                p.x = v00; p.y = v01;
                *(float2*)&Cf[(size_t)row * 1024 + col] = p;
                p.x = v10; p.y = v11;
                *(float2*)&Cf[(size_t)(row + 8) * 1024 + col] = p;
            }
            if (EPI == 0) {
                float be0 = benc[col], be1 = benc[col + 1];
                float wf0 = wfull[col], wf1 = wfull[col + 1];
                float t;
                t = v00 + be0; if (t > 0.f) e0 += t * wf0;
                t = v01 + be1; if (t > 0.f) e0 += t * wf1;
                t = v10 + be0; if (t > 0.f) e1 += t * wf0;
                t = v11 + be1; if (t > 0.f) e1 += t * wf1;
            }
            if (EPI == 2) {
                cs[nt][0] += v00 + v10; cs[nt][1] += v01 + v11;
                cq[nt][0] += v00 * v00 + v10 * v10;
                cq[nt][1] += v01 * v01 + v11 * v11;
            }
        }
        if (EPI == 0) {
            e0 += __shfl_xor_sync(0xffffffffu, e0, 1);
            e0 += __shfl_xor_sync(0xffffffffu, e0, 2);
            e1 += __shfl_xor_sync(0xffffffffu, e1, 1);
            e1 += __shfl_xor_sync(0xffffffffu, e1, 2);
            if ((lane & 3) == 0) {
                atomicAdd(&empty_out[row], e0);
                atomicAdd(&empty_out[row + 8], e1);
            }
        }
    }
    if (EPI == 2) {
#pragma unroll
        for (int nt = 0; nt < 4; nt++) {
#pragma unroll
            for (int j = 0; j < 2; j++) {
                float s = cs[nt][j], q = cq[nt][j];
                s += __shfl_xor_sync(0xffffffffu, s, 4);
                s += __shfl_xor_sync(0xffffffffu, s, 8);
                s += __shfl_xor_sync(0xffffffffu, s, 16);
                q += __shfl_xor_sync(0xffffffffu, q, 4);
                q += __shfl_xor_sync(0xffffffffu, q, 8);
                q += __shfl_xor_sync(0xffffffffu, q, 16);
                if (lane < 4) {
                    int col = n0 + nb + nt * 8 + cpos + j;
                    atomicAdd(&g_bnsum[col], s);
                    atomicAdd(&g_bnsum2[col], q);
                }
            }
        }
    }
}

// ================= HMMA sparse score GEMM (2 N-halves) ============
__global__ void __launch_bounds__(256, 2) hm_scores(
    const __nv_bfloat16* __restrict__ WeH, const __nv_bfloat16* __restrict__ WeL,
    const float* __restrict__ benc, const float* __restrict__ wfull)
{
    int R = g_R;
    int r0 = blockIdx.x * 128;
    if (r0 >= R) return;
    int half = blockIdx.y;

    extern __shared__ __align__(128) char dsm[];
    unsigned sbase = smem_u32(dsm);
    __shared__ int   rb[128];
    __shared__ float red[128][5];

    int tid = threadIdx.x;
    int lane = tid & 31, wid = tid >> 5;
    int mb = (wid >> 2) * 64;
    int nw = wid & 3;
    int nb = nw * 32;

    if (tid < 128) rb[tid] = (r0 + tid < R) ? g_rowb[r0 + tid] : 0;

#pragma unroll
    for (int q = 0; q < 8; q++) {
        int idx = tid + q * 256;
        int mat = idx >> 10, r = (idx >> 3) & 127, c = idx & 7;
        const __nv_bfloat16* src = mat ? g_eRl : g_eRh;
        cpasync16s(sbase + mat * MATB + r * (RSTR * 2) + c * 16,
                   src + (size_t)(r0 + r) * 64 + c * 8);
    }
    auto stage_loadB = [&](int st, int nt) {
        unsigned so = sbase + 2 * MATB + st * 2 * MATB;
#pragma unroll
        for (int q = 0; q < 8; q++) {
            int idx = tid + q * 256;
            int mat = idx >> 10, r = (idx >> 3) & 127, c = idx & 7;
            const __nv_bfloat16* src = mat ? WeL : WeH;
            cpasync16s(so + mat * MATB + r * (RSTR * 2) + c * 16,
                       src + (size_t)(nt * 128 + r) * 64 + c * 8);
        }
    };
    stage_loadB(0, half * 4);
    cp_commit();

    int quad = lane >> 3, rin = lane & 7;
    int a_r = (quad & 1) * 8 + rin;
    int a_c = (quad >> 1) * 8;
    int b_r = (quad >> 1) * 8 + rin;
    int b_c = (quad & 1) * 8;
    int g = lane >> 2;
    int cpos = (lane & 3) * 2;

    float rs[4][2];
#pragma unroll
    for (int mt = 0; mt < 4; mt++) { rs[mt][0] = 0.f; rs[mt][1] = 0.f; }

    for (int tt = 0; tt < 4; tt++) {
        int ti = half * 4 + tt;
        int st = tt & 1;
        if (tt + 1 < 4) { stage_loadB(st ^ 1, ti + 1); cp_commit(); cp_wait1(); }
        else cp_wait0();
        __syncthreads();
        unsigned bo = sbase + 2 * MATB + st * 2 * MATB;

        float acc[4][4][4];
#pragma unroll
        for (int i = 0; i < 4; i++)
#pragma unroll
            for (int j = 0; j < 4; j++)
#pragma unroll
                for (int k = 0; k < 4; k++) acc[i][j][k] = 0.f;

#pragma unroll
        for (int ks = 0; ks < 4; ks++) {
            unsigned fAh[4][4], fAl[4][4], fBh[2][4], fBl[2][4];
#pragma unroll
            for (int mt = 0; mt < 4; mt++) {
                unsigned ad = sbase + ((mb + mt * 16 + a_r) * RSTR + ks * 16 + a_c) * 2;
                LDSM4(fAh[mt], ad);
                LDSM4(fAl[mt], ad + MATB);
            }
#pragma unroll
            for (int np = 0; np < 2; np++) {
                unsigned bd = bo + ((nb + np * 16 + b_r) * RSTR + ks * 16 + b_c) * 2;
                LDSM4(fBh[np], bd);
                LDSM4(fBl[np], bd + MATB);
            }
#pragma unroll
            for (int mt = 0; mt < 4; mt++)
#pragma unroll
                for (int nt = 0; nt < 4; nt++) {
                    unsigned* bh = &fBh[nt >> 1][(nt & 1) * 2];
                    unsigned* bl = &fBl[nt >> 1][(nt & 1) * 2];
                    MMA16816(acc[mt][nt], fAh[mt], bh);
                    MMA16816(acc[mt][nt], fAl[mt], bh);
                    MMA16816(acc[mt][nt], fAh[mt], bl);
                }
        }

#pragma unroll
        for (int nt = 0; nt < 4; nt++) {
            int col = ti * 128 + nb + nt * 8 + cpos;
            float be0 = benc[col], be1 = benc[col + 1];
            float wf0 = wfull[col], wf1 = wfull[col + 1];
#pragma unroll
            for (int mt = 0; mt < 4; mt++) {
                int rl0 = mb + mt * 16 + g;
                float2 d0 = *(const float2*)&g_dec[(size_t)rb[rl0] * 1024 + col];
                float2 d1 = *(const float2*)&g_dec[(size_t)rb[rl0 + 8] * 1024 + col];
                float v;
                v = acc[mt][nt][0] + be0 + d0.x; if (v > 0.f) rs[mt][0] += v * wf0;
                v = acc[mt][nt][1] + be1 + d0.y; if (v > 0.f) rs[mt][0] += v * wf1;
                v = acc[mt][nt][2] + be0 + d1.x; if (v > 0.f) rs[mt][1] += v * wf0;
                v = acc[mt][nt][3] + be1 + d1.y; if (v > 0.f) rs[mt][1] += v * wf1;
            }
        }
        __syncthreads();
    }

#pragma unroll
    for (int mt = 0; mt < 4; mt++) {
#pragma unroll
        for (int hh = 0; hh < 2; hh++) {
            float r = rs[mt][hh];
            r += __shfl_xor_sync(0xffffffffu, r, 1);
            r += __shfl_xor_sync(0xffffffffu, r, 2);
            if ((lane & 3) == 0) red[mb + mt * 16 + g + hh * 8][nw] = r;
        }
    }
    __syncthreads();
    if (tid < 128 && r0 + tid < R) {
        g_scoreP[half][r0 + tid] = red[tid][0] + red[tid][1] + red[tid][2] + red[tid][3];
    }
}

// ================= softmax + ctx + embed (256 thr, parallel gather) ===========
__global__ void k_softctx(const float* __restrict__ bfull, const float* __restrict__ end_pos,
                          const float* __restrict__ rel_pos, const float* __restrict__ Wemb,
                          const float* __restrict__ bemb) {
    int b = blockIdx.x;
    int tid = threadIdx.x;  // 256
    __shared__ float sc[64];
    __shared__ float alpha[64];
    __shared__ float part[4][64];
    __shared__ float sh_se;

    int base = g_base[b], nnz = g_nnz[b];
    float bf0 = bfull[0];
    if (tid < nnz) sc[tid] = g_scoreP[0][base + tid] + g_scoreP[1][base + tid] + bf0;
    if (tid == 0) sh_se = g_empty[b] + bf0;
    __syncthreads();

    if (tid < 32) {
        float se = sh_se;
        float m = se;
        float v0 = (tid < nnz) ? sc[tid] : -1e30f;
        float v1 = (tid + 32 < nnz) ? sc[tid + 32] : -1e30f;
        m = fmaxf(m, fmaxf(v0, v1));
#pragma unroll
        for (int o = 16; o > 0; o >>= 1) m = fmaxf(m, __shfl_xor_sync(0xffffffffu, m, o));
        float e0 = (tid < nnz) ? expf(v0 - m) : 0.f;
        float e1 = (tid + 32 < nnz) ? expf(v1 - m) : 0.f;
        float z = e0 + e1;
#pragma unroll
        for (int o = 16; o > 0; o >>= 1) z += __shfl_xor_sync(0xffffffffu, z, o);
        z += (float)(64 - nnz) * expf(se - m);
        float inv = 1.0f / z;
        if (tid < nnz) alpha[tid] = e0 * inv;
        if (tid + 32 < nnz) alpha[tid + 32] = e1 * inv;
    }
    __syncthreads();

    // ctx partials: 4 slices x 64 dims
    int d = tid & 63, sl = tid >> 6;
    float c = 0.f;
    for (int t = sl; t < nnz; t += 4)
        c += alpha[t] * g_encR[(size_t)(base + t) * 64 + d];
    part[sl][d] = c;
    __syncthreads();

    if (tid < 128) {
        float v;
        if (tid < 64) {
            v = part[0][tid] + part[1][tid] + part[2][tid] + part[3][tid];
        } else if (tid < 68) {
            int j = tid - 64;
            float e = end_pos[b * 2 + 0] * Wemb[0 * 4 + j] + end_pos[b * 2 + 1] * Wemb[1 * 4 + j]
                    + rel_pos[b * 2 + 0] * Wemb[2 * 4 + j] + rel_pos[b * 2 + 1] * Wemb[3 * 4 + j]
                    + bemb[j];
            v = fmaxf(e, 0.f);
        } else {
            v = 0.f;
        }
        __nv_bfloat16 hi = __float2bfloat16(v);
        g_cAh[b * 128 + tid] = hi;
        g_cAl[b * 128 + tid] = __float2bfloat16(v - __bfloat162float(hi));
    }
}

// ================= batchnorm final + apply =================
__global__ void k_bnfinal(const float* __restrict__ gamma, const float* __restrict__ beta) {
    int c = threadIdx.x;
    float mu = g_bnsum[c] / (float)BQ;
    float var = g_bnsum2[c] / (float)BQ - mu * mu;
    float rstd = rsqrtf(var + 1e-5f);
    float ga = gamma[c] * rstd;
    g_bna[c] = ga;
    g_bnb[c] = beta[c] - mu * ga;
}

__global__ void k_bnapply(float* __restrict__ out) {
    int idx = blockIdx.x * blockDim.x + threadIdx.x;
    if (idx < BQ * ATTD) {
        int c = idx & 1023;
        float v = g_x[idx] * g_bna[c] + g_bnb[c];
        out[idx] = v > 0.f ? v : 0.f;
    }
}

// ================= launch =================
extern "C" void kernel_launch(void* const* d_in, const int* in_sizes, int n_in,
                              void* d_out, int out_size) {
    const float* h       = (const float*)d_in[0];
    const float* end_pos = (const float*)d_in[2];
    const float* rel_pos = (const float*)d_in[3];
    const float* Wenc    = (const float*)d_in[4];
    const float* benc    = (const float*)d_in[5];
    const float* Wdec    = (const float*)d_in[6];
    const float* bdec    = (const float*)d_in[7];
    const float* wfull   = (const float*)d_in[8];
    const float* bfull   = (const float*)d_in[9];
    const float* Wemb    = (const float*)d_in[10];
    const float* bemb    = (const float*)d_in[11];
    const float* Wout    = (const float*)d_in[12];
    const float* bout    = (const float*)d_in[13];
    const float* Wmlp    = (const float*)d_in[14];
    const float* bmlp    = (const float*)d_in[15];
    const float* gamma   = (const float*)d_in[16];
    const float* beta    = (const float*)d_in[17];
    float* out = (float*)d_out;

    float *p_dec, *p_x, *p_empty;
    __nv_bfloat16 *p_hAh, *p_hAl, *p_cAh, *p_cAl, *p_mAh, *p_mAl;
    __nv_bfloat16 *p_WdH, *p_WdL, *p_WeH, *p_WeL, *p_WoH, *p_WoL, *p_WmH, *p_WmL;
    cudaGetSymbolAddress((void**)&p_dec,   g_dec);
    cudaGetSymbolAddress((void**)&p_x,     g_x);
    cudaGetSymbolAddress((void**)&p_empty, g_empty);
    cudaGetSymbolAddress((void**)&p_hAh, g_hAh); cudaGetSymbolAddress((void**)&p_hAl, g_hAl);
    cudaGetSymbolAddress((void**)&p_cAh, g_cAh); cudaGetSymbolAddress((void**)&p_cAl, g_cAl);
    cudaGetSymbolAddress((void**)&p_mAh, g_mAh); cudaGetSymbolAddress((void**)&p_mAl, g_mAl);
    cudaGetSymbolAddress((void**)&p_WdH, g_WdH); cudaGetSymbolAddress((void**)&p_WdL, g_WdL);
    cudaGetSymbolAddress((void**)&p_WeH, g_WeH); cudaGetSymbolAddress((void**)&p_WeL, g_WeL);
    cudaGetSymbolAddress((void**)&p_WoH, g_WoH); cudaGetSymbolAddress((void**)&p_WoL, g_WoL);
    cudaGetSymbolAddress((void**)&p_WmH, g_WmH); cudaGetSymbolAddress((void**)&p_WmL, g_WmL);

    const int DSM  = 2 * STAGEB;     // 147456 (hm_gemm)
    const int DSMS = 6 * MATB;       // 110592 (hm_scores)
    cudaFuncSetAttribute(hm_gemm<0>, cudaFuncAttributeMaxDynamicSharedMemorySize, DSM);
    cudaFuncSetAttribute(hm_gemm<1>, cudaFuncAttributeMaxDynamicSharedMemorySize, DSM);
    cudaFuncSetAttribute(hm_gemm<2>, cudaFuncAttributeMaxDynamicSharedMemorySize, DSM);
    cudaFuncSetAttribute(hm_scores,  cudaFuncAttributeMaxDynamicSharedMemorySize, DSMS);

    dim3 gg(8, 16);  // 1024/128 x 2048/128
    dim3 gs(BQ * 64 / 128, 2);

    k_mega<<<1800, 256>>>(h, Wdec, Wenc, Wout, Wmlp);
    k_pool<<<BQ, 256>>>(h, end_pos);
    hm_gemm<0><<<gg, 256, DSM>>>(p_hAh, p_hAl, p_WdH, p_WdL, bdec, 64,
                                 p_dec, nullptr, nullptr, benc, wfull, p_empty);
    hm_scores<<<gs, 256, DSMS>>>(p_WeH, p_WeL, benc, wfull);
    k_softctx<<<BQ, 256>>>(bfull, end_pos, rel_pos, Wemb, bemb);
    hm_gemm<1><<<gg, 256, DSM>>>(p_cAh, p_cAl, p_WoH, p_WoL, bout, 128,
                                 nullptr, p_mAh, p_mAl, nullptr, nullptr, nullptr);
    hm_gemm<2><<<gg, 256, DSM>>>(p_mAh, p_mAl, p_WmH, p_WmL, bmlp, 1024,
                                 p_x, nullptr, nullptr, nullptr, nullptr, nullptr);
    k_bnfinal<<<1, 1024>>>(gamma, beta);
    k_bnapply<<<(BQ * ATTD + 255) / 256, 256>>>(out);
}